// round 15
// baseline (speedup 1.0000x reference)
#include <cuda_runtime.h>
#include <cuda_bf16.h>
#include <cstdint>

// ---------------------------------------------------------------------------
// Scratch (no allocs allowed).
// ---------------------------------------------------------------------------
__device__ unsigned short g_Ah[2 * 512 * 768];   // bf16 hi of [a;b], [z][m][k]
__device__ unsigned short g_Al[2 * 512 * 768];   // bf16 lo
__device__ unsigned short g_Wh[2 * 768 * 768];   // bf16 hi of W1, TRANSPOSED: [z][n][k]
__device__ unsigned short g_Wl[2 * 768 * 768];   // bf16 lo
__device__ float g_ab[2 * 512 * 768];            // [z][m][H] (z=0: ha+b1, z=1: hb)
__device__ float g_part[8 * 4 * 128 * 128 * 2];  // [hsplit][b][s][t][o]

// ---------------------------------------------------------------------------
// Warp-level bf16 MMA (base sm_80+ ISA; compiles under the harness's
// compute_103 target, unlike tcgen05 which needs the 'a' feature set).
// ---------------------------------------------------------------------------
__device__ __forceinline__ void mma16816(float* c, const uint32_t* a, const uint32_t* b) {
    asm volatile(
        "mma.sync.aligned.m16n8k16.row.col.f32.bf16.bf16.f32 "
        "{%0,%1,%2,%3}, {%4,%5,%6,%7}, {%8,%9}, {%0,%1,%2,%3};"
        : "+f"(c[0]), "+f"(c[1]), "+f"(c[2]), "+f"(c[3])
        : "r"(a[0]), "r"(a[1]), "r"(a[2]), "r"(a[3]), "r"(b[0]), "r"(b[1]));
}

// ---------------------------------------------------------------------------
// Fused conversion kernel (one launch):
//  blocks [0, 768):   [a;b] fp32 -> bf16 hi/lo, row-major [z][m][k]
//  blocks [768, 1920): W1 fp32 [1536][768] -> transposed bf16 hi/lo [z][n][k]
// ---------------------------------------------------------------------------
__global__ __launch_bounds__(256) void conv_kernel(const float* __restrict__ a,
                                                   const float* __restrict__ b,
                                                   const float* __restrict__ W1)
{
    const int tid = threadIdx.x;
    if (blockIdx.x < 768) {
        int i = blockIdx.x * 256 + tid;               // float4 index, < 196608
        const float* src = (i < 98304) ? (a + (size_t)i * 4) : (b + (size_t)(i - 98304) * 4);
        float4 v = *(const float4*)src;
        float x[4] = {v.x, v.y, v.z, v.w};
        ushort4 hv, lv;
        unsigned short* hp = &hv.x;
        unsigned short* lp = &lv.x;
        #pragma unroll
        for (int j = 0; j < 4; j++) {
            __nv_bfloat16 h = __float2bfloat16(x[j]);
            __nv_bfloat16 l = __float2bfloat16(x[j] - __bfloat162float(h));
            hp[j] = *(unsigned short*)&h;
            lp[j] = *(unsigned short*)&l;
        }
        *(ushort4*)(g_Ah + (size_t)i * 4) = hv;
        *(ushort4*)(g_Al + (size_t)i * 4) = lv;
    } else {
        __shared__ float tile[32][33];
        const int bxx = blockIdx.x - 768;             // 0..1151
        const int n0 = (bxx % 24) * 32;
        const int k0 = (bxx / 24) * 32;               // global k over 1536
        const int tx = tid & 31, ty = tid >> 5;       // (32, 8)
        #pragma unroll
        for (int i = 0; i < 4; i++)
            tile[ty + 8 * i][tx] = W1[(size_t)(k0 + ty + 8 * i) * 768 + n0 + tx];
        __syncthreads();
        const int z = (k0 >= 768) ? 1 : 0;
        const int kk = k0 - z * 768 + tx;             // k within z
        #pragma unroll
        for (int i = 0; i < 4; i++) {
            int n = n0 + ty + 8 * i;
            float x = tile[tx][ty + 8 * i];           // = W1[k0+tx][n]
            __nv_bfloat16 h = __float2bfloat16(x);
            __nv_bfloat16 l = __float2bfloat16(x - __bfloat162float(h));
            size_t o = (size_t)z * 768 * 768 + (size_t)n * 768 + kk;
            g_Wh[o] = *(unsigned short*)&h;
            g_Wl[o] = *(unsigned short*)&l;
        }
    }
}

// ---------------------------------------------------------------------------
// Tensor-core projection via mma.sync:
//   g_ab[z][m][n] = sum_k A_z[m][k]*W1_z[k][n] (+b1 if z==0)
// bf16-split 3-term: Ah*Wh + Al*Wh + Ah*Wl (Al*Wl ~2^-16, dropped).
// CTA: 32M x 64N, 128 threads = 4 warps (2x2), warp tile 16x32 (1x4 frags).
// K-chunks of 32 with register double-buffer prefetch.
// Grid (16, 12, 2) = 384 CTAs (~2.6/SM): smooth wave tail (vs 192/148) and
// ~4 co-resident CTAs feeding the tensor pipe per SM.
// ---------------------------------------------------------------------------
__global__ __launch_bounds__(128) void mma_proj_kernel(const float* __restrict__ b1)
{
    __shared__ __align__(16) unsigned short AsH[32][40];
    __shared__ __align__(16) unsigned short AsL[32][40];
    __shared__ __align__(16) unsigned short WsH[64][40];
    __shared__ __align__(16) unsigned short WsL[64][40];

    const int tid = threadIdx.x;
    const int wid = tid >> 5;
    const int lid = tid & 31;
    const int g = lid >> 2;              // fragment row group 0..7
    const int t = lid & 3;               // thread-in-group 0..3
    const int m0 = blockIdx.x * 32;
    const int n0 = blockIdx.y * 64;
    const int z  = blockIdx.z;
    const int wm = (wid & 1) * 16;
    const int wn = (wid >> 1) * 32;

    const unsigned short* __restrict__ Ah = g_Ah + (size_t)z * 512 * 768;
    const unsigned short* __restrict__ Al = g_Al + (size_t)z * 512 * 768;
    const unsigned short* __restrict__ Wh = g_Wh + (size_t)z * 768 * 768;
    const unsigned short* __restrict__ Wl = g_Wl + (size_t)z * 768 * 768;

    float acc[4][4];
    #pragma unroll
    for (int nf = 0; nf < 4; nf++)
        #pragma unroll
        for (int q = 0; q < 4; q++) acc[nf][q] = 0.f;

    // Load mapping: row = tid>>2 (0..31), kq = (tid&3)*8.
    const int r0 = tid >> 2;
    const int kq0 = (tid & 3) * 8;

    uint4 pAh, pAl, pWh[2], pWl[2];
    {
        const size_t ga  = (size_t)(m0 + r0) * 768 + kq0;
        const size_t gw0 = (size_t)(n0 + r0) * 768 + kq0;
        const size_t gw1 = (size_t)(n0 + 32 + r0) * 768 + kq0;
        pAh = *(const uint4*)(Ah + ga);
        pAl = *(const uint4*)(Al + ga);
        pWh[0] = *(const uint4*)(Wh + gw0); pWh[1] = *(const uint4*)(Wh + gw1);
        pWl[0] = *(const uint4*)(Wl + gw0); pWl[1] = *(const uint4*)(Wl + gw1);
    }

    #pragma unroll 1
    for (int kb = 0; kb < 768; kb += 32) {
        __syncthreads();
        *(uint4*)&AsH[r0][kq0] = pAh;
        *(uint4*)&AsL[r0][kq0] = pAl;
        *(uint4*)&WsH[r0][kq0]      = pWh[0];
        *(uint4*)&WsH[r0 + 32][kq0] = pWh[1];
        *(uint4*)&WsL[r0][kq0]      = pWl[0];
        *(uint4*)&WsL[r0 + 32][kq0] = pWl[1];
        __syncthreads();

        if (kb + 32 < 768) {
            const size_t ga  = (size_t)(m0 + r0) * 768 + kb + 32 + kq0;
            const size_t gw0 = (size_t)(n0 + r0) * 768 + kb + 32 + kq0;
            const size_t gw1 = (size_t)(n0 + 32 + r0) * 768 + kb + 32 + kq0;
            pAh = *(const uint4*)(Ah + ga);
            pAl = *(const uint4*)(Al + ga);
            pWh[0] = *(const uint4*)(Wh + gw0); pWh[1] = *(const uint4*)(Wh + gw1);
            pWl[0] = *(const uint4*)(Wl + gw0); pWl[1] = *(const uint4*)(Wl + gw1);
        }

        #pragma unroll
        for (int ks = 0; ks < 2; ks++) {
            const int k0 = ks * 16 + t * 2;
            uint32_t ah[4], al[4], bh[4][2], bl[4][2];
            {
                int mb = wm + g;
                ah[0] = *(const uint32_t*)&AsH[mb][k0];
                ah[1] = *(const uint32_t*)&AsH[mb + 8][k0];
                ah[2] = *(const uint32_t*)&AsH[mb][k0 + 8];
                ah[3] = *(const uint32_t*)&AsH[mb + 8][k0 + 8];
                al[0] = *(const uint32_t*)&AsL[mb][k0];
                al[1] = *(const uint32_t*)&AsL[mb + 8][k0];
                al[2] = *(const uint32_t*)&AsL[mb][k0 + 8];
                al[3] = *(const uint32_t*)&AsL[mb + 8][k0 + 8];
            }
            #pragma unroll
            for (int nf = 0; nf < 4; nf++) {
                int nb = wn + nf * 8 + g;
                bh[nf][0] = *(const uint32_t*)&WsH[nb][k0];
                bh[nf][1] = *(const uint32_t*)&WsH[nb][k0 + 8];
                bl[nf][0] = *(const uint32_t*)&WsL[nb][k0];
                bl[nf][1] = *(const uint32_t*)&WsL[nb][k0 + 8];
            }
            #pragma unroll
            for (int nf = 0; nf < 4; nf++) {
                mma16816(acc[nf], ah, bh[nf]);
                mma16816(acc[nf], al, bh[nf]);
                mma16816(acc[nf], ah, bl[nf]);
            }
        }
    }

    // Epilogue: d0/d1 = row g cols 2t,2t+1; d2/d3 = row g+8.
    float* C = g_ab + (size_t)z * 512 * 768;
    const int mr = m0 + wm + g;
    #pragma unroll
    for (int nf = 0; nf < 4; nf++) {
        int n = n0 + wn + nf * 8 + t * 2;
        float2 add = make_float2(0.f, 0.f);
        if (z == 0) add = *(const float2*)(b1 + n);
        *(float2*)(C + (size_t)mr * 768 + n) =
            make_float2(acc[nf][0] + add.x, acc[nf][1] + add.y);
        *(float2*)(C + (size_t)(mr + 8) * 768 + n) =
            make_float2(acc[nf][2] + add.x, acc[nf][3] + add.y);
    }
}

// ---------------------------------------------------------------------------
// Pairwise epilogue: part[hz][b][s][t][o] = sum_{h in chunk} relu(ha[s][h]+hb[t][h]) * W2[h][o]
// 32(s) x 64(t) tile, 256 threads, per-thread 2x4 pairs, H split 8 ways
// (chunk=96, three 32-k phases). Grid (8, 4, 8) = 256 blocks (~1.7/SM).
// ---------------------------------------------------------------------------
__global__ __launch_bounds__(256) void pair_kernel(const float* __restrict__ W2)
{
    const int bx = blockIdx.x;           // 4 s-tiles x 2 t-tiles
    const int bb = blockIdx.y;           // batch
    const int bz = blockIdx.z;           // h split
    const int s0 = (bx & 3) * 32;
    const int t0 = (bx >> 2) * 64;
    const int h0 = bz * 96;

    const float* __restrict__ ha = g_ab + (bb * 128 + s0) * 768 + h0;
    const float* __restrict__ hb = g_ab + 512 * 768 + (bb * 128 + t0) * 768 + h0;

    __shared__ float  sha[32][36];       // [k][s], rows 144B (16B-aligned)
    __shared__ float  shb[32][68];       // [k][t], rows 272B (16B-aligned)
    __shared__ float2 sw2[32];

    const int tid = threadIdx.x;
    const int tx = tid & 15;             // 16 t-groups of 4
    const int ty = tid >> 4;             // 16 s-groups of 2

    float acc[2][4][2];
    #pragma unroll
    for (int i = 0; i < 2; i++)
        #pragma unroll
        for (int j = 0; j < 4; j++) { acc[i][j][0] = 0.f; acc[i][j][1] = 0.f; }

    #pragma unroll 1
    for (int kb = 0; kb < 96; kb += 32) {
        __syncthreads();
        {   // sha: 32 s-rows x 32 k = 256 float4, one per thread
            int si = tid >> 3, kq = (tid & 7) * 4;
            float4 v = *(const float4*)(ha + (size_t)si * 768 + kb + kq);
            sha[kq + 0][si] = v.x; sha[kq + 1][si] = v.y;
            sha[kq + 2][si] = v.z; sha[kq + 3][si] = v.w;
        }
        #pragma unroll
        for (int i = 0; i < 2; i++) {    // shb: 64 t-rows x 32 k = 512 float4
            int f = tid + i * 256;
            int si = f >> 3, kq = (f & 7) * 4;
            float4 w = *(const float4*)(hb + (size_t)si * 768 + kb + kq);
            shb[kq + 0][si] = w.x; shb[kq + 1][si] = w.y;
            shb[kq + 2][si] = w.z; shb[kq + 3][si] = w.w;
        }
        if (tid < 32) sw2[tid] = *(const float2*)(W2 + (h0 + kb + tid) * 2);
        __syncthreads();

        #pragma unroll 4
        for (int k = 0; k < 32; k++) {
            float a0 = sha[k][ty * 2];
            float a1 = sha[k][ty * 2 + 1];
            float4 bv = *(const float4*)&shb[k][tx * 4];
            float2 w  = sw2[k];
            float aa[2] = {a0, a1};
            float bb4[4] = {bv.x, bv.y, bv.z, bv.w};
            #pragma unroll
            for (int i = 0; i < 2; i++)
                #pragma unroll
                for (int j = 0; j < 4; j++) {
                    float x = aa[i] + bb4[j];
                    float v = fmaxf(x, 0.0f);
                    acc[i][j][0] += v * w.x;
                    acc[i][j][1] += v * w.y;
                }
        }
    }

    float* P = g_part + (size_t)(bz * 4 + bb) * (128 * 128 * 2);
    #pragma unroll
    for (int i = 0; i < 2; i++)
        #pragma unroll
        for (int j = 0; j < 4; j++) {
            int s = s0 + ty * 2 + i;
            int t = t0 + tx * 4 + j;
            *(float2*)(P + ((size_t)s * 128 + t) * 2) = make_float2(acc[i][j][0], acc[i][j][1]);
        }
}

// ---------------------------------------------------------------------------
// Reduce the 8 h-split partials + output bias. float4 per thread (2 pairs).
// ---------------------------------------------------------------------------
__global__ __launch_bounds__(256) void reduce_kernel(const float* __restrict__ b2,
                                                     float* __restrict__ out)
{
    int idx = blockIdx.x * 256 + threadIdx.x;   // 0..32767, 2 pairs each
    float2 bb = *(const float2*)b2;
    float4 acc = make_float4(bb.x, bb.y, bb.x, bb.y);
    #pragma unroll
    for (int zz = 0; zz < 8; zz++) {
        float4 p = *(const float4*)(g_part + (size_t)zz * (4 * 128 * 128 * 2) + (size_t)idx * 4);
        acc.x += p.x; acc.y += p.y; acc.z += p.z; acc.w += p.w;
    }
    *(float4*)(out + (size_t)idx * 4) = acc;
}

extern "C" void kernel_launch(void* const* d_in, const int* in_sizes, int n_in,
                              void* d_out, int out_size)
{
    const float* a  = (const float*)d_in[0];
    const float* b  = (const float*)d_in[1];
    const float* W1 = (const float*)d_in[2];
    const float* b1 = (const float*)d_in[3];
    const float* W2 = (const float*)d_in[4];
    const float* b2 = (const float*)d_in[5];
    float* out = (float*)d_out;

    conv_kernel<<<1920, 256>>>(a, b, W1);
    mma_proj_kernel<<<dim3(16, 12, 2), 128>>>(b1);
    pair_kernel<<<dim3(8, 4, 8), 256>>>(W2);
    reduce_kernel<<<128, 256>>>(b2, out);
}

// round 16
// speedup vs baseline: 1.1273x; 1.1273x over previous
#include <cuda_runtime.h>
#include <cuda_bf16.h>
#include <cstdint>

// ---------------------------------------------------------------------------
// Scratch (no allocs allowed).
// ---------------------------------------------------------------------------
__device__ unsigned short g_Ah[2 * 512 * 768];   // bf16 hi of [a;b], [z][m][k]
__device__ unsigned short g_Al[2 * 512 * 768];   // bf16 lo
__device__ unsigned short g_Wh[2 * 768 * 768];   // bf16 hi of W1, TRANSPOSED: [z][n][k]
__device__ unsigned short g_Wl[2 * 768 * 768];   // bf16 lo
__device__ float g_ab[2 * 512 * 768];            // [z][m][H] (z=0: ha+b1, z=1: hb)
__device__ float g_part[8 * 4 * 128 * 128 * 2];  // [hsplit][b][s][t][o]

// ---------------------------------------------------------------------------
// Warp-level bf16 MMA (base sm_80+ ISA; compiles under the harness's
// compute_103 target, unlike tcgen05 which needs the 'a' feature set).
// ---------------------------------------------------------------------------
__device__ __forceinline__ void mma16816(float* c, const uint32_t* a, const uint32_t* b) {
    asm volatile(
        "mma.sync.aligned.m16n8k16.row.col.f32.bf16.bf16.f32 "
        "{%0,%1,%2,%3}, {%4,%5,%6,%7}, {%8,%9}, {%0,%1,%2,%3};"
        : "+f"(c[0]), "+f"(c[1]), "+f"(c[2]), "+f"(c[3])
        : "r"(a[0]), "r"(a[1]), "r"(a[2]), "r"(a[3]), "r"(b[0]), "r"(b[1]));
}

__device__ __forceinline__ void cpa16(uint32_t saddr, const void* g) {
    asm volatile("cp.async.cg.shared.global [%0], [%1], 16;" :: "r"(saddr), "l"(g) : "memory");
}
#define CP_COMMIT() asm volatile("cp.async.commit_group;" ::: "memory")
#define CP_WAIT(n)  asm volatile("cp.async.wait_group %0;" :: "n"(n) : "memory")

// ---------------------------------------------------------------------------
// Fused conversion kernel (one launch):
//  blocks [0, 768):   [a;b] fp32 -> bf16 hi/lo, row-major [z][m][k]
//  blocks [768, 1920): W1 fp32 [1536][768] -> transposed bf16 hi/lo [z][n][k]
// ---------------------------------------------------------------------------
__global__ __launch_bounds__(256) void conv_kernel(const float* __restrict__ a,
                                                   const float* __restrict__ b,
                                                   const float* __restrict__ W1)
{
    const int tid = threadIdx.x;
    if (blockIdx.x < 768) {
        int i = blockIdx.x * 256 + tid;               // float4 index, < 196608
        const float* src = (i < 98304) ? (a + (size_t)i * 4) : (b + (size_t)(i - 98304) * 4);
        float4 v = *(const float4*)src;
        float x[4] = {v.x, v.y, v.z, v.w};
        ushort4 hv, lv;
        unsigned short* hp = &hv.x;
        unsigned short* lp = &lv.x;
        #pragma unroll
        for (int j = 0; j < 4; j++) {
            __nv_bfloat16 h = __float2bfloat16(x[j]);
            __nv_bfloat16 l = __float2bfloat16(x[j] - __bfloat162float(h));
            hp[j] = *(unsigned short*)&h;
            lp[j] = *(unsigned short*)&l;
        }
        *(ushort4*)(g_Ah + (size_t)i * 4) = hv;
        *(ushort4*)(g_Al + (size_t)i * 4) = lv;
    } else {
        __shared__ float tile[32][33];
        const int bxx = blockIdx.x - 768;             // 0..1151
        const int n0 = (bxx % 24) * 32;
        const int k0 = (bxx / 24) * 32;               // global k over 1536
        const int tx = tid & 31, ty = tid >> 5;       // (32, 8)
        #pragma unroll
        for (int i = 0; i < 4; i++)
            tile[ty + 8 * i][tx] = W1[(size_t)(k0 + ty + 8 * i) * 768 + n0 + tx];
        __syncthreads();
        const int z = (k0 >= 768) ? 1 : 0;
        const int kk = k0 - z * 768 + tx;             // k within z
        #pragma unroll
        for (int i = 0; i < 4; i++) {
            int n = n0 + ty + 8 * i;
            float x = tile[tx][ty + 8 * i];           // = W1[k0+tx][n]
            __nv_bfloat16 h = __float2bfloat16(x);
            __nv_bfloat16 l = __float2bfloat16(x - __bfloat162float(h));
            size_t o = (size_t)z * 768 * 768 + (size_t)n * 768 + kk;
            g_Wh[o] = *(unsigned short*)&h;
            g_Wl[o] = *(unsigned short*)&l;
        }
    }
}

// ---------------------------------------------------------------------------
// Tensor-core projection via mma.sync (R14 tiling + cp.async 3-stage pipe):
//   g_ab[z][m][n] = sum_k A_z[m][k]*W1_z[k][n] (+b1 if z==0)
// bf16-split 3-term: Ah*Wh + Al*Wh + Ah*Wl (Al*Wl ~2^-16, dropped).
// CTA: 64M x 64N, 128 threads = 4 warps (2x2), warp tile 32x32 (2x4 frags).
// K-chunks of 32; 3-stage cp.async pipeline: chunk k+2 loads in flight under
// chunk k's MMA section; ONE __syncthreads per chunk.
// Grid (8, 12, 2) = 192 CTAs.
//
// Stage layout (20 KB each, 3 stages = 60 KB dynamic smem):
//   [0, 5120)      AsH 64 rows x 40 elems (80B row stride, data 32 elems)
//   [5120, 10240)  AsL
//   [10240, 15360) WsH
//   [15360, 20480) WsL
// ---------------------------------------------------------------------------
#define STG_BYTES 20480
#define ROW_B 80

__global__ __launch_bounds__(128) void mma_proj_kernel(const float* __restrict__ b1)
{
    extern __shared__ __align__(16) char dynsmem[];
    const uint32_t sbase = (uint32_t)__cvta_generic_to_shared(dynsmem);

    const int tid = threadIdx.x;
    const int wid = tid >> 5;
    const int lid = tid & 31;
    const int g = lid >> 2;              // fragment row group 0..7
    const int t = lid & 3;               // thread-in-group 0..3
    const int m0 = blockIdx.x * 64;
    const int n0 = blockIdx.y * 64;
    const int z  = blockIdx.z;
    const int wm = (wid & 1) * 32;
    const int wn = (wid >> 1) * 32;

    const unsigned short* __restrict__ Ah = g_Ah + (size_t)z * 512 * 768;
    const unsigned short* __restrict__ Al = g_Al + (size_t)z * 512 * 768;
    const unsigned short* __restrict__ Wh = g_Wh + (size_t)z * 768 * 768;
    const unsigned short* __restrict__ Wl = g_Wl + (size_t)z * 768 * 768;

    float acc[2][4][4];
    #pragma unroll
    for (int mf = 0; mf < 2; mf++)
        #pragma unroll
        for (int nf = 0; nf < 4; nf++)
            #pragma unroll
            for (int q = 0; q < 4; q++) acc[mf][nf][q] = 0.f;

    // cp.async mapping: each thread covers rows r0 and r0+32 at kq0, for all
    // four matrices (8 x 16B per thread per stage).
    const int r0  = tid >> 2;            // 0..31
    const int kq0 = (tid & 3) * 8;       // 0,8,16,24

    auto issue_stage = [&](int st, int kb) {
        const uint32_t s0 = sbase + st * STG_BYTES;
        const uint32_t o0 = r0 * ROW_B + kq0 * 2;
        const uint32_t o1 = (r0 + 32) * ROW_B + kq0 * 2;
        const size_t ga0 = (size_t)(m0 + r0) * 768 + kb + kq0;
        const size_t ga1 = (size_t)(m0 + 32 + r0) * 768 + kb + kq0;
        const size_t gw0 = (size_t)(n0 + r0) * 768 + kb + kq0;
        const size_t gw1 = (size_t)(n0 + 32 + r0) * 768 + kb + kq0;
        cpa16(s0 + o0,          Ah + ga0);
        cpa16(s0 + o1,          Ah + ga1);
        cpa16(s0 + 5120 + o0,   Al + ga0);
        cpa16(s0 + 5120 + o1,   Al + ga1);
        cpa16(s0 + 10240 + o0,  Wh + gw0);
        cpa16(s0 + 10240 + o1,  Wh + gw1);
        cpa16(s0 + 15360 + o0,  Wl + gw0);
        cpa16(s0 + 15360 + o1,  Wl + gw1);
        CP_COMMIT();
    };

    issue_stage(0, 0);
    issue_stage(1, 32);

    #pragma unroll 1
    for (int kc = 0; kc < 24; kc++) {
        CP_WAIT(1);                      // oldest group (chunk kc) complete
        __syncthreads();                 // visible to all warps; prev MMA done
        if (kc + 2 < 24) issue_stage((kc + 2) % 3, (kc + 2) * 32);

        const char* S = dynsmem + (kc % 3) * STG_BYTES;
        const char* SAH = S;
        const char* SAL = S + 5120;
        const char* SWH = S + 10240;
        const char* SWL = S + 15360;

        #pragma unroll
        for (int ks = 0; ks < 2; ks++) {
            const int k0 = ks * 16 + t * 2;
            uint32_t ah[2][4], al[2][4], bh[4][2], bl[4][2];
            #pragma unroll
            for (int mf = 0; mf < 2; mf++) {
                int mb = wm + mf * 16 + g;
                ah[mf][0] = *(const uint32_t*)(SAH + mb * ROW_B + k0 * 2);
                ah[mf][1] = *(const uint32_t*)(SAH + (mb + 8) * ROW_B + k0 * 2);
                ah[mf][2] = *(const uint32_t*)(SAH + mb * ROW_B + (k0 + 8) * 2);
                ah[mf][3] = *(const uint32_t*)(SAH + (mb + 8) * ROW_B + (k0 + 8) * 2);
                al[mf][0] = *(const uint32_t*)(SAL + mb * ROW_B + k0 * 2);
                al[mf][1] = *(const uint32_t*)(SAL + (mb + 8) * ROW_B + k0 * 2);
                al[mf][2] = *(const uint32_t*)(SAL + mb * ROW_B + (k0 + 8) * 2);
                al[mf][3] = *(const uint32_t*)(SAL + (mb + 8) * ROW_B + (k0 + 8) * 2);
            }
            #pragma unroll
            for (int nf = 0; nf < 4; nf++) {
                int nb = wn + nf * 8 + g;
                bh[nf][0] = *(const uint32_t*)(SWH + nb * ROW_B + k0 * 2);
                bh[nf][1] = *(const uint32_t*)(SWH + nb * ROW_B + (k0 + 8) * 2);
                bl[nf][0] = *(const uint32_t*)(SWL + nb * ROW_B + k0 * 2);
                bl[nf][1] = *(const uint32_t*)(SWL + nb * ROW_B + (k0 + 8) * 2);
            }
            #pragma unroll
            for (int mf = 0; mf < 2; mf++)
                #pragma unroll
                for (int nf = 0; nf < 4; nf++) {
                    mma16816(acc[mf][nf], ah[mf], bh[nf]);
                    mma16816(acc[mf][nf], al[mf], bh[nf]);
                    mma16816(acc[mf][nf], ah[mf], bl[nf]);
                }
        }
    }

    // Epilogue: d0/d1 = row g cols 2t,2t+1; d2/d3 = row g+8.
    float* C = g_ab + (size_t)z * 512 * 768;
    #pragma unroll
    for (int mf = 0; mf < 2; mf++) {
        int mr = m0 + wm + mf * 16 + g;
        #pragma unroll
        for (int nf = 0; nf < 4; nf++) {
            int n = n0 + wn + nf * 8 + t * 2;
            float2 add = make_float2(0.f, 0.f);
            if (z == 0) add = *(const float2*)(b1 + n);
            *(float2*)(C + (size_t)mr * 768 + n) =
                make_float2(acc[mf][nf][0] + add.x, acc[mf][nf][1] + add.y);
            *(float2*)(C + (size_t)(mr + 8) * 768 + n) =
                make_float2(acc[mf][nf][2] + add.x, acc[mf][nf][3] + add.y);
        }
    }
}

// ---------------------------------------------------------------------------
// Pairwise epilogue: part[hz][b][s][t][o] = sum_{h in chunk} relu(ha[s][h]+hb[t][h]) * W2[h][o]
// 32(s) x 64(t) tile, 256 threads, per-thread 2x4 pairs, H split 8 ways
// (chunk=96, three 32-k phases). Grid (8, 4, 8) = 256 blocks (~1.7/SM).
// ---------------------------------------------------------------------------
__global__ __launch_bounds__(256) void pair_kernel(const float* __restrict__ W2)
{
    const int bx = blockIdx.x;           // 4 s-tiles x 2 t-tiles
    const int bb = blockIdx.y;           // batch
    const int bz = blockIdx.z;           // h split
    const int s0 = (bx & 3) * 32;
    const int t0 = (bx >> 2) * 64;
    const int h0 = bz * 96;

    const float* __restrict__ ha = g_ab + (bb * 128 + s0) * 768 + h0;
    const float* __restrict__ hb = g_ab + 512 * 768 + (bb * 128 + t0) * 768 + h0;

    __shared__ float  sha[32][36];       // [k][s], rows 144B (16B-aligned)
    __shared__ float  shb[32][68];       // [k][t], rows 272B (16B-aligned)
    __shared__ float2 sw2[32];

    const int tid = threadIdx.x;
    const int tx = tid & 15;             // 16 t-groups of 4
    const int ty = tid >> 4;             // 16 s-groups of 2

    float acc[2][4][2];
    #pragma unroll
    for (int i = 0; i < 2; i++)
        #pragma unroll
        for (int j = 0; j < 4; j++) { acc[i][j][0] = 0.f; acc[i][j][1] = 0.f; }

    #pragma unroll 1
    for (int kb = 0; kb < 96; kb += 32) {
        __syncthreads();
        {   // sha: 32 s-rows x 32 k = 256 float4, one per thread
            int si = tid >> 3, kq = (tid & 7) * 4;
            float4 v = *(const float4*)(ha + (size_t)si * 768 + kb + kq);
            sha[kq + 0][si] = v.x; sha[kq + 1][si] = v.y;
            sha[kq + 2][si] = v.z; sha[kq + 3][si] = v.w;
        }
        #pragma unroll
        for (int i = 0; i < 2; i++) {    // shb: 64 t-rows x 32 k = 512 float4
            int f = tid + i * 256;
            int si = f >> 3, kq = (f & 7) * 4;
            float4 w = *(const float4*)(hb + (size_t)si * 768 + kb + kq);
            shb[kq + 0][si] = w.x; shb[kq + 1][si] = w.y;
            shb[kq + 2][si] = w.z; shb[kq + 3][si] = w.w;
        }
        if (tid < 32) sw2[tid] = *(const float2*)(W2 + (h0 + kb + tid) * 2);
        __syncthreads();

        #pragma unroll 4
        for (int k = 0; k < 32; k++) {
            float a0 = sha[k][ty * 2];
            float a1 = sha[k][ty * 2 + 1];
            float4 bv = *(const float4*)&shb[k][tx * 4];
            float2 w  = sw2[k];
            float aa[2] = {a0, a1};
            float bb4[4] = {bv.x, bv.y, bv.z, bv.w};
            #pragma unroll
            for (int i = 0; i < 2; i++)
                #pragma unroll
                for (int j = 0; j < 4; j++) {
                    float x = aa[i] + bb4[j];
                    float v = fmaxf(x, 0.0f);
                    acc[i][j][0] += v * w.x;
                    acc[i][j][1] += v * w.y;
                }
        }
    }

    float* P = g_part + (size_t)(bz * 4 + bb) * (128 * 128 * 2);
    #pragma unroll
    for (int i = 0; i < 2; i++)
        #pragma unroll
        for (int j = 0; j < 4; j++) {
            int s = s0 + ty * 2 + i;
            int t = t0 + tx * 4 + j;
            *(float2*)(P + ((size_t)s * 128 + t) * 2) = make_float2(acc[i][j][0], acc[i][j][1]);
        }
}

// ---------------------------------------------------------------------------
// Reduce the 8 h-split partials + output bias. float4 per thread (2 pairs).
// ---------------------------------------------------------------------------
__global__ __launch_bounds__(256) void reduce_kernel(const float* __restrict__ b2,
                                                     float* __restrict__ out)
{
    int idx = blockIdx.x * 256 + threadIdx.x;   // 0..32767, 2 pairs each
    float2 bb = *(const float2*)b2;
    float4 acc = make_float4(bb.x, bb.y, bb.x, bb.y);
    #pragma unroll
    for (int zz = 0; zz < 8; zz++) {
        float4 p = *(const float4*)(g_part + (size_t)zz * (4 * 128 * 128 * 2) + (size_t)idx * 4);
        acc.x += p.x; acc.y += p.y; acc.z += p.z; acc.w += p.w;
    }
    *(float4*)(out + (size_t)idx * 4) = acc;
}

extern "C" void kernel_launch(void* const* d_in, const int* in_sizes, int n_in,
                              void* d_out, int out_size)
{
    const float* a  = (const float*)d_in[0];
    const float* b  = (const float*)d_in[1];
    const float* W1 = (const float*)d_in[2];
    const float* b1 = (const float*)d_in[3];
    const float* W2 = (const float*)d_in[4];
    const float* b2 = (const float*)d_in[5];
    float* out = (float*)d_out;

    static bool attr_set = false;
    if (!attr_set) {
        cudaFuncSetAttribute(mma_proj_kernel,
                             cudaFuncAttributeMaxDynamicSharedMemorySize, 3 * STG_BYTES);
        attr_set = true;
    }

    conv_kernel<<<1920, 256>>>(a, b, W1);
    mma_proj_kernel<<<dim3(8, 12, 2), 128, 3 * STG_BYTES>>>(b1);
    pair_kernel<<<dim3(8, 4, 8), 256>>>(W2);
    reduce_kernel<<<128, 256>>>(b2, out);
}